// round 5
// baseline (speedup 1.0000x reference)
#include <cuda_runtime.h>
#include <math.h>

#define B_   32
#define TT_  512
#define TM_  2048
#define D_   512
#define M_   80
#define NEGF (-1e9f)

#define HEXP_ELEMS (B_*TM_*D_)       /* 33554432 */
#define LOSS_OFF   HEXP_ELEMS
#define DUR_OFF    (HEXP_ELEMS + 1)

// ------------------- device scratch (no allocation allowed) -------------------
__device__ float g_hw[B_*TT_*M_];     // [b*Tt+i][80] = h @ W
__device__ float g_hb[B_*TT_];        // h @ b_proj
__device__ float g_S[(size_t)B_*TM_*TT_]; // [b][j][i] masked scores (128 MB)
__device__ int   g_idx[B_*TM_];       // frame -> token index
__device__ float g_lsq[B_];
__device__ float g_lcnt[B_];

// ------------------- f32x2 helpers -------------------
__device__ __forceinline__ unsigned long long pk2(float x, float y) {
    unsigned long long r;
    asm("mov.b64 %0, {%1,%2};" : "=l"(r) : "f"(x), "f"(y));
    return r;
}
__device__ __forceinline__ float2 upk2(unsigned long long v) {
    float2 r;
    asm("mov.b64 {%0,%1}, %2;" : "=f"(r.x), "=f"(r.y) : "l"(v));
    return r;
}
#define FMA2(d, a, b, c) asm("fma.rn.f32x2 %0, %1, %2, %3;" : "=l"(d) : "l"(a), "l"(b), "l"(c))

// =================== K1: hw[b,i,m] = sum_d h[b,i,d] * w[d,m] ===================
// grid 256 blocks (64 rows each), 256 threads. Tiles: rows 64 x K-chunk 64 x M 80.
__global__ void __launch_bounds__(256) k1_hw(const float* __restrict__ h,
                                             const float* __restrict__ w) {
    __shared__ float hS[64*68];   // [r][d] stride 68
    __shared__ float wS[64*84];   // [d][m] stride 84
    int tid  = threadIdx.x;
    int row0 = blockIdx.x * 64;            // global row = b*Tt + i
    int tx = tid & 15;                     // m group: m0 = tx*5
    int ty = tid >> 4;                     // row group: r0 = ty*4
    float acc[4][5];
#pragma unroll
    for (int r = 0; r < 4; r++)
#pragma unroll
        for (int m = 0; m < 5; m++) acc[r][m] = 0.f;

    for (int dc = 0; dc < D_; dc += 64) {
        // h chunk: 64 rows x 64 d = 1024 float4
#pragma unroll
        for (int k = 0; k < 4; k++) {
            int l = tid + k*256;
            int r = l >> 4, d4 = l & 15;
            float4 v = *(const float4*)&h[(size_t)(row0 + r)*D_ + dc + d4*4];
            *(float4*)&hS[r*68 + d4*4] = v;
        }
        // w chunk: 64 d x 80 m = 1280 float4
#pragma unroll
        for (int k = 0; k < 5; k++) {
            int l = tid + k*256;
            int d = l / 20, m4 = l % 20;
            float4 v = *(const float4*)&w[(size_t)(dc + d)*M_ + m4*4];
            *(float4*)&wS[d*84 + m4*4] = v;
        }
        __syncthreads();
#pragma unroll 8
        for (int d = 0; d < 64; d++) {
            float a0 = hS[(ty*4+0)*68 + d];
            float a1 = hS[(ty*4+1)*68 + d];
            float a2 = hS[(ty*4+2)*68 + d];
            float a3 = hS[(ty*4+3)*68 + d];
#pragma unroll
            for (int m = 0; m < 5; m++) {
                float bv = wS[d*84 + tx*5 + m];
                acc[0][m] += a0*bv; acc[1][m] += a1*bv;
                acc[2][m] += a2*bv; acc[3][m] += a3*bv;
            }
        }
        __syncthreads();
    }
#pragma unroll
    for (int r = 0; r < 4; r++)
#pragma unroll
        for (int m = 0; m < 5; m++)
            g_hw[(size_t)(row0 + ty*4 + r)*M_ + tx*5 + m] = acc[r][m];
}

// =================== K1b: hb[row] = sum_d h[row,d] * b_proj[d] ===================
__global__ void k1_hb(const float* __restrict__ h, const float* __restrict__ bp) {
    int gw   = (blockIdx.x*blockDim.x + threadIdx.x) >> 5;
    int lane = threadIdx.x & 31;
    if (gw >= B_*TT_) return;
    const float4* hr = (const float4*)&h[(size_t)gw * D_];
    const float4* b4 = (const float4*)bp;
    float s = 0.f;
    for (int k = lane; k < D_/4; k += 32) {
        float4 a = hr[k], c = b4[k];
        s += a.x*c.x + a.y*c.y + a.z*c.z + a.w*c.w;
    }
#pragma unroll
    for (int o = 16; o; o >>= 1) s += __shfl_down_sync(0xffffffffu, s, o);
    if (lane == 0) g_hb[gw] = s;
}

// =================== K2: S[b][j][i] = masked(hw[b,i,:] . mel[b,:,j] + hb[b,i]) ===================
// grid (4 i-blocks, 16 j-blocks, 32 b), 256 threads, dynamic smem 83520 B.
__global__ void __launch_bounds__(256) k2_attn(const float* __restrict__ mel,
                                               const int* __restrict__ tlv,
                                               const int* __restrict__ mlv) {
    extern __shared__ float sm2[];
    float* melS = sm2;            // [80][132]
    float* hwS  = sm2 + 80*132;   // [80][129]
    int b  = blockIdx.z;
    int ml = mlv[b];
    int j0 = blockIdx.y * 128;
    if (j0 >= ml) return;
    int i0  = blockIdx.x * 128;
    int tid = threadIdx.x;
    int tx  = tid & 15;   // i = i0 + tx + 16*k
    int ty  = tid >> 4;   // j = j0 + ty + 16*jk

    const float* melB = mel + (size_t)b*M_*TM_;
#pragma unroll
    for (int k = 0; k < 10; k++) {           // 80x128 = 2560 float4
        int l = tid + k*256;
        int m = l >> 5, j4 = l & 31;
        float4 v = *(const float4*)&melB[(size_t)m*TM_ + j0 + j4*4];
        *(float4*)&melS[m*132 + j4*4] = v;
    }
    const float* hwB = g_hw + (size_t)b*TT_*M_;
#pragma unroll
    for (int k = 0; k < 40; k++) {           // transpose 128x80 scalars
        int l = tid + k*256;
        int m = l % 80, ii = l / 80;
        hwS[m*129 + ii] = hwB[(size_t)(i0+ii)*M_ + m];
    }
    __syncthreads();

    unsigned long long acc[8][4];
#pragma unroll
    for (int jk = 0; jk < 8; jk++)
#pragma unroll
        for (int p = 0; p < 4; p++) acc[jk][p] = 0ull;

#pragma unroll 2
    for (int m = 0; m < M_; m++) {
        float hv[8];
#pragma unroll
        for (int k = 0; k < 8; k++) hv[k] = hwS[m*129 + tx + 16*k];
        unsigned long long hp[4];
#pragma unroll
        for (int p = 0; p < 4; p++) hp[p] = pk2(hv[2*p], hv[2*p+1]);
#pragma unroll
        for (int jk = 0; jk < 8; jk++) {
            float mv = melS[m*132 + ty + 16*jk];
            unsigned long long mp = pk2(mv, mv);
#pragma unroll
            for (int p = 0; p < 4; p++) FMA2(acc[jk][p], hp[p], mp, acc[jk][p]);
        }
    }

    int tlb = tlv[b];
    float hbv[8];
    bool  msk[8];
#pragma unroll
    for (int k = 0; k < 8; k++) {
        int ig = i0 + tx + 16*k;
        hbv[k] = g_hb[b*TT_ + ig];
        msk[k] = (ig < tlb);
    }
#pragma unroll
    for (int jk = 0; jk < 8; jk++) {
        int j = j0 + ty + 16*jk;
        if (j < ml) {
            float* row = g_S + ((size_t)b*TM_ + j)*TT_ + i0;
#pragma unroll
            for (int p = 0; p < 4; p++) {
                float2 v = upk2(acc[jk][p]);
                int k0 = 2*p, k1 = 2*p+1;
                row[tx + 16*k0] = msk[k0] ? (v.x + hbv[k0]) : NEGF;
                row[tx + 16*k1] = msk[k1] ? (v.y + hbv[k1]) : NEGF;
            }
        }
    }
}

// =================== K3: MAS DP + backtrack + durations/loss/idx ===================
// grid 32 (one block per batch), 512 threads, dynamic smem ~135.4 KB.
__global__ void __launch_bounds__(512) k3_dp(const float* __restrict__ ldp,
                                             const int* __restrict__ tlv,
                                             const int* __restrict__ mlv,
                                             float* __restrict__ out) {
    extern __shared__ unsigned int dsm[];
    unsigned int* ch   = dsm;                         // [512][65]
    float*        bnd  = (float*)(dsm + 512*65);      // [2][16]
    unsigned int* dur  = (unsigned int*)(bnd + 32);   // [512]
    unsigned int* wsum = dur + 512;                   // [16]
    float*        red  = (float*)(wsum + 16);         // [16]

    int b    = blockIdx.x;
    int i    = threadIdx.x;
    int lane = i & 31, wid = i >> 5;
    int tl = tlv[b], ml = mlv[b];
    const float* Sb = g_S + (size_t)b*TM_*TT_;

    float q = (i == 0) ? Sb[0] : NEGF;
    unsigned int cw = 0;
    int p = 0;
    float c[8], n[8];
#pragma unroll
    for (int k = 0; k < 8; k++) {
        int j = 1 + k;
        c[k] = (j < ml) ? Sb[(size_t)j*TT_ + i] : 0.f;
    }

    for (int j0 = 1; j0 < ml; j0 += 8) {
#pragma unroll
        for (int k = 0; k < 8; k++) {          // prefetch next group (deep MLP)
            int j = j0 + 8 + k;
            n[k] = (j < ml) ? Sb[(size_t)j*TT_ + i] : 0.f;
        }
#pragma unroll
        for (int k = 0; k < 8; k++) {
            int j = j0 + k;
            if (j < ml) {                       // uniform across block
                if (lane == 31) bnd[p*16 + wid] = q;
                __syncthreads();
                float up = __shfl_up_sync(0xffffffffu, q, 1);
                if (lane == 0) up = (wid == 0) ? NEGF : bnd[p*16 + wid - 1];
                unsigned int take = (up > q) ? 1u : 0u;
                q = c[k] + fmaxf(q, up);
                cw |= take << (j & 31);
                if ((j & 31) == 31) { ch[i*65 + (j >> 5)] = cw; cw = 0; }
                p ^= 1;
            }
        }
#pragma unroll
        for (int k = 0; k < 8; k++) c[k] = n[k];
    }
    if (((ml - 1) & 31) != 31) ch[i*65 + ((ml - 1) >> 5)] = cw;
    dur[i] = 0;
    __syncthreads();

    if (i == 0) {                               // serial CLZ run-scan backtrack
        int ii = tl - 1, j = ml - 1;
        while (j >= 0) {
            if (ii == 0) { dur[0] += (unsigned)(j + 1); break; }
            unsigned int w = ch[ii*65 + (j >> 5)];
            int bit = j & 31;
            if (bit != 31) w &= (2u << bit) - 1u;
            if (w == 0) { dur[ii] += (unsigned)(bit + 1); j -= bit + 1; }
            else {
                int hb = 31 - __clz(w);
                int jp = (j & ~31) + hb;         // nearest column <= j with choice=1
                dur[ii] += (unsigned)(j - jp + 1);
                ii -= 1;
                j = jp - 1;
            }
        }
    }
    __syncthreads();

    unsigned int d = dur[i];
    out[DUR_OFF + b*TT_ + i] = (float)d;

    // loss partial
    float part = 0.f;
    if (i < tl) {
        float lg = logf(fmaxf((float)d, 1.0f));
        float df = ldp[b*TT_ + i] - lg;
        part = df * df;
    }
#pragma unroll
    for (int o = 16; o; o >>= 1) part += __shfl_down_sync(0xffffffffu, part, o);
    if (lane == 0) red[wid] = part;

    // inclusive scan of dur -> frame index scatter
    unsigned int v = d;
#pragma unroll
    for (int o = 1; o < 32; o <<= 1) {
        unsigned int t = __shfl_up_sync(0xffffffffu, v, o);
        if (lane >= o) v += t;
    }
    if (lane == 31) wsum[wid] = v;
    __syncthreads();
    if (i < 16) {
        unsigned int s = wsum[i];
#pragma unroll
        for (int o = 1; o < 16; o <<= 1) {
            unsigned int t = __shfl_up_sync(0x0000ffffu, s, o);
            if ((i & 15) >= o) s += t;
        }
        wsum[i] = s;
        float ls = red[i];
#pragma unroll
        for (int o = 8; o; o >>= 1) ls += __shfl_down_sync(0x0000ffffu, ls, o);
        if (i == 0) { g_lsq[b] = ls; g_lcnt[b] = (float)tl; }
    }
    __syncthreads();
    unsigned int base = (wid == 0) ? 0u : wsum[wid - 1];
    unsigned int cend = base + v;
    unsigned int cstart = cend - d;
    for (unsigned int j = cstart; j < cend; j++) g_idx[b*TM_ + j] = i;
}

// =================== K4: final loss reduce ===================
__global__ void k4_loss(float* __restrict__ out) {
    int t = threadIdx.x;  // 32
    float s = g_lsq[t], cc = g_lcnt[t];
#pragma unroll
    for (int o = 16; o; o >>= 1) {
        s  += __shfl_down_sync(0xffffffffu, s, o);
        cc += __shfl_down_sync(0xffffffffu, cc, o);
    }
    if (t == 0) out[LOSS_OFF] = s / cc;
}

// =================== K5: length-regulate expansion ===================
// grid (1, 1024, 32), 256 threads: 2 frames/block, float4 rows.
__global__ void __launch_bounds__(256) k5_expand(const float* __restrict__ h,
                                                 const int* __restrict__ mlv,
                                                 float* __restrict__ out) {
    int b  = blockIdx.z;
    int j  = blockIdx.y * 2 + (threadIdx.x >> 7);
    int c4 = threadIdx.x & 127;
    int ml = mlv[b];
    float4 v;
    if (j < ml) {
        int idx = g_idx[b*TM_ + j];
        v = *(const float4*)&h[((size_t)(b*TT_ + idx))*D_ + c4*4];
    } else {
        v = make_float4(0.f, 0.f, 0.f, 0.f);
    }
    *(float4*)&out[((size_t)(b*TM_ + j))*D_ + c4*4] = v;
}

// =================== host launcher ===================
extern "C" void kernel_launch(void* const* d_in, const int* in_sizes, int n_in,
                              void* d_out, int out_size) {
    const float* h_text = (const float*)d_in[0];   // [32,512,512]
    const float* mel    = (const float*)d_in[1];   // [32,80,2048]
    const int*   tl     = (const int*)  d_in[2];   // [32]
    const int*   mlv    = (const int*)  d_in[3];   // [32]
    const float* w_proj = (const float*)d_in[4];   // [512,80]
    const float* b_proj = (const float*)d_in[5];   // [512]
    const float* ldp    = (const float*)d_in[6];   // [32,512]
    float* out = (float*)d_out;

    const int K2_SMEM = (80*132 + 80*129) * 4;                        // 83520
    const int K3_SMEM = (512*65 + 512 + 16 + 16) * 4 + 32 * 4;        // 135456
    cudaFuncSetAttribute(k2_attn, cudaFuncAttributeMaxDynamicSharedMemorySize, K2_SMEM);
    cudaFuncSetAttribute(k3_dp,   cudaFuncAttributeMaxDynamicSharedMemorySize, K3_SMEM);

    k1_hw<<<256, 256>>>(h_text, w_proj);
    k1_hb<<<2048, 256>>>(h_text, b_proj);
    k2_attn<<<dim3(4, 16, 32), 256, K2_SMEM>>>(mel, tl, mlv);
    k3_dp<<<32, 512, K3_SMEM>>>(ldp, tl, mlv, out);
    k4_loss<<<1, 32>>>(out);
    k5_expand<<<dim3(1, 1024, 32), 256>>>(h_text, mlv, out);
}